// round 11
// baseline (speedup 1.0000x reference)
#include <cuda_runtime.h>
#include <stdint.h>

#define B_DIM 4
#define C_DIM 2
#define E_DIM 256
#define L_DIM 16000
#define W_DIM 40
#define STEP  20
#define T_DIM ((L_DIM - 1) * STEP + W_DIM)   // 320020
#define NT    128
#define LTILES (L_DIM / NT)        // 125

#define KC      16
#define NSTAGE  (E_DIM / KC)       // 16
#define PITCH_B 40                 // words; tig coef 40 mod 32 = 8 -> 8*tig+g conflict-free
#define PITCH_D 40

#define SB_WORDS (E_DIM * PITCH_B)     // 10240  (basis tile, whole K)
#define SD_WORDS (NT * PITCH_D)        // 5120   (epilogue overlay)
#define SMEM_BYTES (SB_WORDS * 4)      // 40960

#define NSTRIPS (B_DIM * C_DIM * (LTILES - 1))     // 992 CTA-boundary strips

__device__ __forceinline__ uint32_t f2tf32(float f) {
    uint32_t u;
    asm("cvt.rna.tf32.f32 %0, %1;" : "=r"(u) : "f"(f));
    return u;
}
__device__ __forceinline__ void mma_tf32(float* d, const uint32_t* a, const uint32_t* b) {
    asm volatile(
        "mma.sync.aligned.m16n8k8.row.col.f32.tf32.tf32.f32 "
        "{%0,%1,%2,%3}, {%4,%5,%6,%7}, {%8,%9}, {%0,%1,%2,%3};"
        : "+f"(d[0]), "+f"(d[1]), "+f"(d[2]), "+f"(d[3])
        : "r"(a[0]), "r"(a[1]), "r"(a[2]), "r"(a[3]), "r"(b[0]), "r"(b[1]));
}

// ---------- zero only the CTA-boundary strips (atomic targets) ----------
__global__ void zero_strips_kernel(float* __restrict__ out) {
    int i = blockIdx.x * blockDim.x + threadIdx.x;
    if (i < NSTRIPS * STEP) {
        int j  = i % STEP;
        int s  = i / STEP;
        int bc = s / (LTILES - 1);
        int k  = s % (LTILES - 1) + 1;            // boundary ltile 1..124
        out[(size_t)bc * T_DIM + (size_t)k * NT * STEP + j] = 0.f;
    }
}

__global__ void __launch_bounds__(NT)
decoder_kernel(const float* __restrict__ mix,
               const float* __restrict__ mask,
               const float* __restrict__ basis,
               float* __restrict__ out) {
    __shared__ __align__(16) uint32_t smem[SB_WORDS];
    uint32_t* sB = smem;                               // tf32 basis [e][w], pitch 40
    float*    sD = reinterpret_cast<float*>(smem);     // epilogue overlay

    const int tid  = threadIdx.x;
    const int wid  = tid >> 5;
    const int lane = tid & 31;
    const int g    = lane >> 2;
    const int tig  = lane & 3;

    const int bc    = blockIdx.x & 7;      // bc minor -> paired-c CTAs share mix in L2
    const int ltile = blockIdx.x >> 3;
    const int b     = bc >> 1;
    const int c     = bc & 1;
    const int l     = ltile * NT + tid;

    // ---- preload whole basis into SMEM as tf32 (one time) ----
    for (int i = tid; i < W_DIM * E_DIM; i += NT) {
        int w = i >> 8;            // basis is [W][E], E=256
        int e = i & 255;
        sB[e * PITCH_B + w] = f2tf32(basis[i]);
    }
    __syncthreads();

    // ---- direct-fragment pointers: all frag offsets are immediates ----
    // A-frag element (er, j): e = tig + 4*er ; l = lbase + mbase + g + J[j], J = {0,8,16,24}
    const int mbase = wid * 32;
    const float* pm = mix  + (size_t)b * E_DIM * L_DIM + (size_t)tig * L_DIM
                    + (size_t)ltile * NT + mbase + g;
    const float* pk = mask + ((size_t)b * C_DIM + c) * E_DIM * L_DIM + (size_t)tig * L_DIM
                    + (size_t)ltile * NT + mbase + g;
    const uint32_t* pb = sB + tig * PITCH_B + g;       // + st*640 + ks*320 + nt*8 (+160)

    float acc[2][5][4];
#pragma unroll
    for (int mt = 0; mt < 2; ++mt)
#pragma unroll
        for (int nt = 0; nt < 5; ++nt)
#pragma unroll
            for (int r = 0; r < 4; ++r) acc[mt][nt][r] = 0.f;

    // ---- software pipeline: raw mv/kv for stage st loaded during stage st-1 ----
    float mv[16], kv[16];
#pragma unroll
    for (int er = 0; er < 4; ++er)
#pragma unroll
        for (int j = 0; j < 4; ++j) {
            mv[er * 4 + j] = pm[(size_t)er * 4 * L_DIM + j * 8];
            kv[er * 4 + j] = pk[(size_t)er * 4 * L_DIM + j * 8];
        }
    pm += (size_t)KC * L_DIM;
    pk += (size_t)KC * L_DIM;

#pragma unroll 1
    for (int st = 0; st < NSTAGE; ++st) {
        // convert current stage's A values (waits on last stage's prefetch only)
        uint32_t av[16];
#pragma unroll
        for (int i = 0; i < 16; ++i) av[i] = f2tf32(mv[i] * kv[i]);

        // prefetch next stage (32 LDGs fly under the MMAs below; no barriers)
        if (st + 1 < NSTAGE) {
#pragma unroll
            for (int er = 0; er < 4; ++er)
#pragma unroll
                for (int j = 0; j < 4; ++j) {
                    mv[er * 4 + j] = pm[(size_t)er * 4 * L_DIM + j * 8];
                    kv[er * 4 + j] = pk[(size_t)er * 4 * L_DIM + j * 8];
                }
            pm += (size_t)KC * L_DIM;
            pk += (size_t)KC * L_DIM;
        }

        const uint32_t* pbs = pb + st * (KC * PITCH_B);
#pragma unroll
        for (int ks = 0; ks < 2; ++ks) {
            uint32_t a[2][4];
#pragma unroll
            for (int mt = 0; mt < 2; ++mt) {
                a[mt][0] = av[(2 * ks)     * 4 + 2 * mt];
                a[mt][1] = av[(2 * ks)     * 4 + 2 * mt + 1];
                a[mt][2] = av[(2 * ks + 1) * 4 + 2 * mt];
                a[mt][3] = av[(2 * ks + 1) * 4 + 2 * mt + 1];
            }
            uint32_t bf[5][2];
#pragma unroll
            for (int nt = 0; nt < 5; ++nt) {
                bf[nt][0] = pbs[ks * 8 * PITCH_B + nt * 8];
                bf[nt][1] = pbs[ks * 8 * PITCH_B + nt * 8 + 4 * PITCH_B];
            }
#pragma unroll
            for (int mt = 0; mt < 2; ++mt)
#pragma unroll
                for (int nt = 0; nt < 5; ++nt)
                    mma_tf32(acc[mt][nt], a[mt], bf[nt]);
        }
    }

    // ---- write frags to D tile in SMEM (overlay; basis dead after all MMAs) ----
    __syncthreads();
#pragma unroll
    for (int mt = 0; mt < 2; ++mt) {
#pragma unroll
        for (int nt = 0; nt < 5; ++nt) {
            int row = mbase + mt * 16 + g;
            int col = nt * 8 + 2 * tig;
            *reinterpret_cast<float2*>(&sD[row * PITCH_D + col]) =
                make_float2(acc[mt][nt][0], acc[mt][nt][1]);
            *reinterpret_cast<float2*>(&sD[(row + 8) * PITCH_D + col]) =
                make_float2(acc[mt][nt][2], acc[mt][nt][3]);
        }
    }
    __syncthreads();

    // ---- fused overlap-add epilogue (thread tid <-> l) ----
    // segment l = frame[l][0:20] + frame[l-1][20:40]; frame[l-1] is sD row tid-1.
    float lo[STEP], up[STEP];
#pragma unroll
    for (int q = 0; q < 5; ++q) {
        float4 v = *reinterpret_cast<float4*>(&sD[tid * PITCH_D + q * 4]);
        lo[4 * q] = v.x; lo[4 * q + 1] = v.y; lo[4 * q + 2] = v.z; lo[4 * q + 3] = v.w;
    }
    if (tid > 0) {
#pragma unroll
        for (int q = 0; q < 5; ++q) {
            float4 v = *reinterpret_cast<float4*>(&sD[(tid - 1) * PITCH_D + STEP + q * 4]);
            up[4 * q] = v.x; up[4 * q + 1] = v.y; up[4 * q + 2] = v.z; up[4 * q + 3] = v.w;
        }
    }

    const size_t base = (size_t)bc * T_DIM + (size_t)l * STEP;
    if (tid > 0) {
#pragma unroll
        for (int j = 0; j < STEP; ++j) out[base + j] = lo[j] + up[j];
    } else if (l == 0) {
#pragma unroll
        for (int j = 0; j < STEP; ++j) out[base + j] = lo[j];
    } else {
#pragma unroll
        for (int j = 0; j < STEP; ++j) atomicAdd(&out[base + j], lo[j]);   // boundary strip
    }

    if (tid == NT - 1) {          // my own upper half has no in-CTA consumer
        float hi[STEP];
#pragma unroll
        for (int q = 0; q < 5; ++q) {
            float4 v = *reinterpret_cast<float4*>(&sD[tid * PITCH_D + STEP + q * 4]);
            hi[4 * q] = v.x; hi[4 * q + 1] = v.y; hi[4 * q + 2] = v.z; hi[4 * q + 3] = v.w;
        }
        if (l == L_DIM - 1) {     // global tail: sole contributor
#pragma unroll
            for (int j = 0; j < STEP; ++j) out[base + STEP + j] = hi[j];
        } else {                  // boundary strip
#pragma unroll
            for (int j = 0; j < STEP; ++j) atomicAdd(&out[base + STEP + j], hi[j]);
        }
    }
}

extern "C" void kernel_launch(void* const* d_in, const int* in_sizes, int n_in,
                              void* d_out, int out_size) {
    // Identify inputs by element count for robustness.
    const float *mix = nullptr, *mask = nullptr, *basis = nullptr;
    for (int i = 0; i < n_in; ++i) {
        long long s = in_sizes[i];
        if (s == (long long)B_DIM * E_DIM * L_DIM)              mix   = (const float*)d_in[i];
        else if (s == (long long)B_DIM * C_DIM * E_DIM * L_DIM) mask  = (const float*)d_in[i];
        else if (s == (long long)W_DIM * E_DIM)                 basis = (const float*)d_in[i];
    }
    float* out = (float*)d_out;

    zero_strips_kernel<<<(NSTRIPS * STEP + 255) / 256, 256>>>(out);

    decoder_kernel<<<B_DIM * C_DIM * LTILES, NT>>>(mix, mask, basis, out);
}

// round 12
// speedup vs baseline: 1.3457x; 1.3457x over previous
#include <cuda_runtime.h>
#include <stdint.h>

#define B_DIM 4
#define C_DIM 2
#define E_DIM 256
#define L_DIM 16000
#define W_DIM 40
#define STEP  20
#define T_DIM ((L_DIM - 1) * STEP + W_DIM)   // 320020
#define NT    256
#define MTILE 128                  // l's per CTA
#define LTILES (L_DIM / MTILE)     // 125

#define KC      16
#define NSTAGE  (E_DIM / KC)       // 16
#define NBUF    3
#define PITCH_A 136                // words; mod 32 == 8 -> conflict-free frag reads
#define PITCH_B 20                 // words; (nt*8+g)*20 + tig distinct mod 32
#define PITCH_D 40

#define SA_WORDS (KC * PITCH_A)        // 2176 per buffer
#define SB_WORDS (W_DIM * PITCH_B)     // 800 per buffer
#define MIX_OFF  0                                  // 3 bufs
#define MSK_OFF  (NBUF * SA_WORDS)                  // 6528; 3 bufs x 2 channels
#define BAS_OFF  (MSK_OFF + 2 * NBUF * SA_WORDS)    // 19584
#define LOOP_WORDS (BAS_OFF + NBUF * SB_WORDS)      // 21984
#define SMEM_BYTES (LOOP_WORDS * 4)                 // 87936

#define NSTRIPS (B_DIM * C_DIM * (LTILES - 1))      // 992 CTA-boundary strips

__device__ __forceinline__ uint32_t f2tf32(float f) {
    uint32_t u;
    asm("cvt.rna.tf32.f32 %0, %1;" : "=r"(u) : "f"(f));
    return u;
}
__device__ __forceinline__ void mma_tf32(float* d, const uint32_t* a, const uint32_t* b) {
    asm volatile(
        "mma.sync.aligned.m16n8k8.row.col.f32.tf32.tf32.f32 "
        "{%0,%1,%2,%3}, {%4,%5,%6,%7}, {%8,%9}, {%0,%1,%2,%3};"
        : "+f"(d[0]), "+f"(d[1]), "+f"(d[2]), "+f"(d[3])
        : "r"(a[0]), "r"(a[1]), "r"(a[2]), "r"(a[3]), "r"(b[0]), "r"(b[1]));
}
__device__ __forceinline__ void cp16(uint32_t dst_smem, const void* src) {
    asm volatile("cp.async.cg.shared.global [%0], [%1], 16;" :: "r"(dst_smem), "l"(src));
}
__device__ __forceinline__ void cp_commit() {
    asm volatile("cp.async.commit_group;" ::: "memory");
}
__device__ __forceinline__ void cp_wait1() {
    asm volatile("cp.async.wait_group 1;" ::: "memory");
}

// ---------- zero only the CTA-boundary strips (atomic targets) ----------
__global__ void zero_strips_kernel(float* __restrict__ out) {
    int i = blockIdx.x * blockDim.x + threadIdx.x;
    if (i < NSTRIPS * STEP) {
        int j  = i % STEP;
        int s  = i / STEP;
        int bc = s / (LTILES - 1);
        int k  = s % (LTILES - 1) + 1;            // boundary ltile 1..124
        out[(size_t)bc * T_DIM + (size_t)k * MTILE * STEP + j] = 0.f;
    }
}

__global__ void __launch_bounds__(NT, 2)
decoder_kernel(const float* __restrict__ mix,
               const float* __restrict__ mask,
               const float* __restrict__ basis,
               float* __restrict__ out) {
    extern __shared__ __align__(16) uint32_t smem[];
    const uint32_t smem_base = (uint32_t)__cvta_generic_to_shared(smem);
    float* sF = reinterpret_cast<float*>(smem);
    float* sD = sF;                                  // epilogue overlay (2*128*40 = 10240 w)

    const int tid  = threadIdx.x;
    const int wid  = tid >> 5;
    const int lane = tid & 31;
    const int g    = lane >> 2;
    const int tig  = lane & 3;

    const int b     = blockIdx.x & 3;
    const int ltile = blockIdx.x >> 2;

    const float* pmix = mix + (size_t)b * E_DIM * L_DIM + (size_t)ltile * MTILE;
    const float* pmk0 = mask + ((size_t)b * C_DIM + 0) * E_DIM * L_DIM + (size_t)ltile * MTILE;
    const float* pmk1 = pmk0 + (size_t)E_DIM * L_DIM;

    // staging coords: mix -> 2 quads/thread, mask -> my channel, 4 quads/thread
    const int mch  = tid >> 7;             // which mask channel this thread stages
    const int mt7  = tid & 127;
    const float* pmk = (mch == 0) ? pmk0 : pmk1;

    float acc[2][5][4];
#pragma unroll
    for (int mt = 0; mt < 2; ++mt)
#pragma unroll
        for (int nt = 0; nt < 5; ++nt)
#pragma unroll
            for (int r = 0; r < 4; ++r) acc[mt][nt][r] = 0.f;

    // ---- stage issuer (cp.async) ----
    auto issue_stage = [&](int s) {
        if (s < NSTAGE) {
            const int buf = s % NBUF;
            const size_t eoff = (size_t)s * KC * L_DIM;
            const uint32_t dmix = smem_base + (MIX_OFF + buf * SA_WORDS) * 4;
            const uint32_t dmsk = smem_base + (MSK_OFF + (buf * 2 + mch) * SA_WORDS) * 4;
            // mix: 512 quads over 256 threads (2 each)
#pragma unroll
            for (int i = 0; i < 2; ++i) {
                const int q = tid + (i << 8);
                const int e = q >> 5, l4 = (q & 31) * 4;
                cp16(dmix + (uint32_t)(e * PITCH_A + l4) * 4,
                     pmix + eoff + (size_t)e * L_DIM + l4);
            }
            // mask (my channel): 512 quads over 128 threads (4 each)
#pragma unroll
            for (int i = 0; i < 4; ++i) {
                const int q = mt7 + (i << 7);
                const int e = q >> 5, l4 = (q & 31) * 4;
                cp16(dmsk + (uint32_t)(e * PITCH_A + l4) * 4,
                     pmk + eoff + (size_t)e * L_DIM + l4);
            }
            // basis chunk: 160 quads
            if (tid < 160) {
                const int w = tid >> 2, be = (tid & 3) * 4;
                const uint32_t dbas = smem_base + (BAS_OFF + buf * SB_WORDS) * 4;
                cp16(dbas + (uint32_t)(w * PITCH_B + be) * 4,
                     basis + (size_t)w * E_DIM + s * KC + be);
            }
        }
        cp_commit();   // empty groups past the end keep wait counts uniform
    };

    // prologue: stages 0 and 1 in flight
    issue_stage(0);
    issue_stage(1);

    const int ch    = wid >> 2;            // compute channel of this warp
    const int mbase = (wid & 3) * 32;

#pragma unroll 1
    for (int st = 0; st < NSTAGE; ++st) {
        cp_wait1();                 // stage st landed (st+1 still in flight)
        __syncthreads();            // stage st visible; all warps past mma(st-1)
        issue_stage(st + 2);        // buf (st+2)%3 == (st-1)%3: freed by the sync above

        const int buf = st % NBUF;
        const float* fMix = sF + MIX_OFF + buf * SA_WORDS;
        const float* fMsk = sF + MSK_OFF + (buf * 2 + ch) * SA_WORDS;
        const float* fB   = sF + BAS_OFF + buf * SB_WORDS;

#pragma unroll
        for (int ks = 0; ks < 2; ++ks) {
            const int kb = ks * 8;
            const int r1 = (kb + tig) * PITCH_A;
            const int r2 = (kb + tig + 4) * PITCH_A;
            uint32_t a[2][4];
#pragma unroll
            for (int mt = 0; mt < 2; ++mt) {
                const int m0 = mbase + mt * 16 + g;
                a[mt][0] = f2tf32(fMix[r1 + m0]     * fMsk[r1 + m0]);
                a[mt][1] = f2tf32(fMix[r1 + m0 + 8] * fMsk[r1 + m0 + 8]);
                a[mt][2] = f2tf32(fMix[r2 + m0]     * fMsk[r2 + m0]);
                a[mt][3] = f2tf32(fMix[r2 + m0 + 8] * fMsk[r2 + m0 + 8]);
            }
            uint32_t bf[5][2];
#pragma unroll
            for (int nt = 0; nt < 5; ++nt) {
                bf[nt][0] = f2tf32(fB[(nt * 8 + g) * PITCH_B + kb + tig]);
                bf[nt][1] = f2tf32(fB[(nt * 8 + g) * PITCH_B + kb + tig + 4]);
            }
#pragma unroll
            for (int mt = 0; mt < 2; ++mt)
#pragma unroll
                for (int nt = 0; nt < 5; ++nt)
                    mma_tf32(acc[mt][nt], a[mt], bf[nt]);
        }
    }

    // ---- write frags to D tile in SMEM (overlay; loop buffers dead) ----
    __syncthreads();
#pragma unroll
    for (int mt = 0; mt < 2; ++mt) {
#pragma unroll
        for (int nt = 0; nt < 5; ++nt) {
            int row = ch * MTILE + mbase + mt * 16 + g;
            int col = nt * 8 + 2 * tig;
            *reinterpret_cast<float2*>(&sD[row * PITCH_D + col]) =
                make_float2(acc[mt][nt][0], acc[mt][nt][1]);
            *reinterpret_cast<float2*>(&sD[(row + 8) * PITCH_D + col]) =
                make_float2(acc[mt][nt][2], acc[mt][nt][3]);
        }
    }
    __syncthreads();

    // ---- fused overlap-add epilogue: thread -> (channel tid>>7, row tid&127) ----
    const int r  = tid & 127;
    const int rr = mch * MTILE + r;        // sD row
    const int l  = ltile * MTILE + r;

    float lo[STEP], up[STEP];
#pragma unroll
    for (int q = 0; q < 5; ++q) {
        float4 v = *reinterpret_cast<float4*>(&sD[rr * PITCH_D + q * 4]);
        lo[4 * q] = v.x; lo[4 * q + 1] = v.y; lo[4 * q + 2] = v.z; lo[4 * q + 3] = v.w;
    }
    if (r > 0) {
#pragma unroll
        for (int q = 0; q < 5; ++q) {
            float4 v = *reinterpret_cast<float4*>(&sD[(rr - 1) * PITCH_D + STEP + q * 4]);
            up[4 * q] = v.x; up[4 * q + 1] = v.y; up[4 * q + 2] = v.z; up[4 * q + 3] = v.w;
        }
    }

    const size_t base = ((size_t)b * C_DIM + mch) * T_DIM + (size_t)l * STEP;
    if (r > 0) {
#pragma unroll
        for (int j = 0; j < STEP; ++j) out[base + j] = lo[j] + up[j];
    } else if (l == 0) {
#pragma unroll
        for (int j = 0; j < STEP; ++j) out[base + j] = lo[j];
    } else {
#pragma unroll
        for (int j = 0; j < STEP; ++j) atomicAdd(&out[base + j], lo[j]);   // boundary strip
    }

    if (r == MTILE - 1) {         // my own upper half has no in-CTA consumer
        float hi[STEP];
#pragma unroll
        for (int q = 0; q < 5; ++q) {
            float4 v = *reinterpret_cast<float4*>(&sD[rr * PITCH_D + STEP + q * 4]);
            hi[4 * q] = v.x; hi[4 * q + 1] = v.y; hi[4 * q + 2] = v.z; hi[4 * q + 3] = v.w;
        }
        if (l == L_DIM - 1) {     // global tail: sole contributor
#pragma unroll
            for (int j = 0; j < STEP; ++j) out[base + STEP + j] = hi[j];
        } else {                  // boundary strip
#pragma unroll
            for (int j = 0; j < STEP; ++j) atomicAdd(&out[base + STEP + j], hi[j]);
        }
    }
}

extern "C" void kernel_launch(void* const* d_in, const int* in_sizes, int n_in,
                              void* d_out, int out_size) {
    // Identify inputs by element count for robustness.
    const float *mix = nullptr, *mask = nullptr, *basis = nullptr;
    for (int i = 0; i < n_in; ++i) {
        long long s = in_sizes[i];
        if (s == (long long)B_DIM * E_DIM * L_DIM)              mix   = (const float*)d_in[i];
        else if (s == (long long)B_DIM * C_DIM * E_DIM * L_DIM) mask  = (const float*)d_in[i];
        else if (s == (long long)W_DIM * E_DIM)                 basis = (const float*)d_in[i];
    }
    float* out = (float*)d_out;

    zero_strips_kernel<<<(NSTRIPS * STEP + 255) / 256, 256>>>(out);

    cudaFuncSetAttribute(decoder_kernel,
                         cudaFuncAttributeMaxDynamicSharedMemorySize, SMEM_BYTES);
    decoder_kernel<<<B_DIM * LTILES, NT, SMEM_BYTES>>>(mix, mask, basis, out);
}